// round 6
// baseline (speedup 1.0000x reference)
#include <cuda_runtime.h>
#include <cuda_bf16.h>
#include <cuda_fp16.h>
#include <cstdint>

// LightGCN via pull-based CSR gather, fp16 intermediate embeddings.
// deg = clamp(segsum(w by dst), 1); norm = deg^-1/2
// repeat 2x: h = segsum((h*norm)[src] * w, by dst) * norm
// out = mean(h0, h1, h2)

#define NN    100000
#define EE    1600000
#define SCAN_B 256                       // scan block size
#define NB_MAX 512                       // >= ceil(NN/SCAN_B) = 391

__device__ float   g_deg[NN];
__device__ int     g_cnt[NN];
__device__ float   g_norm[NN];
__device__ int     g_rowptr[NN + 1];
__device__ int     g_cursor[NN];
__device__ int     g_bsum[NB_MAX];
__device__ float2  g_edge[EE];               // .x = __int_as_float(src), .y = w
__device__ __half2 g_ha[(size_t)NN * 32];    // layer-1 input (h0*norm), fp16
__device__ __half2 g_hb[(size_t)NN * 32];    // layer-2 input (h1*norm), fp16

// ---------------- CSR build ----------------

__global__ void k_zero(int n) {
    int i = blockIdx.x * blockDim.x + threadIdx.x;
    if (i < n) { g_deg[i] = 0.0f; g_cnt[i] = 0; }
}

__global__ void k_hist(const float* __restrict__ w,
                       const int* __restrict__ dst, int e) {
    int i = blockIdx.x * blockDim.x + threadIdx.x;
    if (i >= e) return;
    int d = dst[i];
    atomicAdd(&g_deg[d], w[i]);
    atomicAdd(&g_cnt[d], 1);
}

// Pass A: per-block exclusive scan (256 wide) of g_cnt -> g_rowptr; totals -> g_bsum
__global__ void k_scanA(int n) {
    __shared__ int sh[8];
    int i = blockIdx.x * SCAN_B + threadIdx.x;
    int lane = threadIdx.x & 31, wid = threadIdx.x >> 5;
    int v = (i < n) ? g_cnt[i] : 0;
    int x = v;
    #pragma unroll
    for (int o = 1; o < 32; o <<= 1) {
        int y = __shfl_up_sync(0xffffffffu, x, o);
        if (lane >= o) x += y;
    }
    if (lane == 31) sh[wid] = x;
    __syncthreads();
    if (threadIdx.x == 0) {
        int acc = 0;
        #pragma unroll
        for (int k = 0; k < 8; k++) { int t = sh[k]; sh[k] = acc; acc += t; }
        g_bsum[blockIdx.x] = acc;                 // block total
    }
    __syncthreads();
    int excl = x - v + sh[wid];
    if (i < n) g_rowptr[i] = excl;
}

// Pass B+C+prep fused (256 threads/block, nb blocks):
//  - per-block prefix over g_bsum[0..blockIdx) (warp 0)
//  - finalize rowptr/cursor, compute norm (into smem)
//  - prep this block's 256 nodes: out = h; g_ha = fp16(h * norm)
__global__ void k_scanC(const float4* __restrict__ h, float4* __restrict__ out,
                        int n, int e) {
    __shared__ float s_norm[SCAN_B];
    __shared__ int s_off;
    int t = threadIdx.x;
    int lane = t & 31;
    int base = blockIdx.x * SCAN_B;

    if (t < 32) {
        int acc = 0;
        for (int k = lane; k < blockIdx.x; k += 32) acc += g_bsum[k];
        #pragma unroll
        for (int o = 16; o > 0; o >>= 1)
            acc += __shfl_down_sync(0xffffffffu, acc, o);
        if (lane == 0) s_off = acc;
    }
    __syncthreads();
    int off = s_off;

    int i = base + t;
    float nm = 0.0f;
    if (i < n) {
        int r = g_rowptr[i] + off;
        g_rowptr[i] = r;
        g_cursor[i] = r;
        nm = rsqrtf(fmaxf(g_deg[i], 1.0f));
        g_norm[i] = nm;
        if (i == 0) g_rowptr[n] = e;
    }
    s_norm[t] = nm;
    __syncthreads();

    // prep: nodes [base, base+256): 16 float4 each, coalesced, 16 iters
    #pragma unroll
    for (int k = 0; k < 16; k++) {
        int idx4 = base * 16 + t + k * SCAN_B;    // global float4 index
        int node = idx4 >> 4;
        if (node >= n) break;
        float nrm = s_norm[node - base];
        float4 v = h[idx4];
        out[idx4] = v;
        g_ha[(size_t)idx4 * 2]     = __floats2half2_rn(v.x * nrm, v.y * nrm);
        g_ha[(size_t)idx4 * 2 + 1] = __floats2half2_rn(v.z * nrm, v.w * nrm);
    }
}

__global__ void k_fill(const int* __restrict__ src,
                       const int* __restrict__ dst,
                       const float* __restrict__ w, int e) {
    int i = blockIdx.x * blockDim.x + threadIdx.x;
    if (i >= e) return;
    int d = dst[i];
    int pos = atomicAdd(&g_cursor[d], 1);
    g_edge[pos] = make_float2(__int_as_float(src[i]), w[i]);
}

// ---------------- gather layers ----------------

// Warp per node; lane owns dims [2*lane, 2*lane+1] (one __half2).
// Edge staging: each lane loads one edge of a 32-edge chunk (coalesced),
// then (src, w) are distributed via shfl -> gather loads have no
// load->load dependency (high MLP).
// LAYER=0: read g_ha; h1 = sum*norm; out += h1; g_hb = fp16(h1*norm)
// LAYER=1: read g_hb; h2 = sum*norm; out = (out + h2) / 3
template <int LAYER>
__global__ void k_gather(float2* __restrict__ out, int n) {
    const __half2* hin = (LAYER == 0) ? g_ha : g_hb;
    int warp = (blockIdx.x * blockDim.x + threadIdx.x) >> 5;
    int lane = threadIdx.x & 31;
    if (warp >= n) return;
    int beg = g_rowptr[warp];
    int end = g_rowptr[warp + 1];

    float ax = 0.f, ay = 0.f;
    for (int jb = beg; jb < end; jb += 32) {
        int m = end - jb; if (m > 32) m = 32;
        float2 e = make_float2(0.0f, 0.0f);
        if (lane < m) e = g_edge[jb + lane];
        int   es = __float_as_int(e.x);
        float ew = e.y;
        if (m == 32) {
            #pragma unroll
            for (int k = 0; k < 32; k++) {
                int   s  = __shfl_sync(0xffffffffu, es, k);
                float wt = __shfl_sync(0xffffffffu, ew, k);
                float2 v = __half22float2(hin[(size_t)s * 32 + lane]);
                ax += v.x * wt; ay += v.y * wt;
            }
        } else {
            for (int k = 0; k < m; k++) {
                int   s  = __shfl_sync(0xffffffffu, es, k);
                float wt = __shfl_sync(0xffffffffu, ew, k);
                float2 v = __half22float2(hin[(size_t)s * 32 + lane]);
                ax += v.x * wt; ay += v.y * wt;
            }
        }
    }

    float nm = g_norm[warp];
    float hx = ax * nm, hy = ay * nm;
    size_t idx = (size_t)warp * 32 + lane;
    float2 o = out[idx];
    if (LAYER == 1) {
        const float third = 1.0f / 3.0f;
        out[idx] = make_float2((o.x + hx) * third, (o.y + hy) * third);
    } else {
        out[idx] = make_float2(o.x + hx, o.y + hy);
        g_hb[idx] = __floats2half2_rn(hx * nm, hy * nm);
    }
}

extern "C" void kernel_launch(void* const* d_in, const int* in_sizes, int n_in,
                              void* d_out, int out_size) {
    const float* h   = (const float*)d_in[0];
    const float* w   = (const float*)d_in[1];
    const int*   src = (const int*)d_in[2];
    const int*   dst = (const int*)d_in[3];
    float* out = (float*)d_out;

    const int N  = in_sizes[0] / 64;   // 100000
    const int E  = in_sizes[1];        // 1600000
    const int B  = 256;
    const int nb = (N + SCAN_B - 1) / SCAN_B;   // 391

    k_zero <<<(N + B - 1) / B, B>>>(N);
    k_hist <<<(E + B - 1) / B, B>>>(w, dst, E);
    k_scanA<<<nb, SCAN_B>>>(N);
    k_scanC<<<nb, SCAN_B>>>((const float4*)h, (float4*)out, N, E);
    k_fill <<<(E + B - 1) / B, B>>>(src, dst, w, E);

    const int warpsPerBlock = B / 32;
    const int grid = (N + warpsPerBlock - 1) / warpsPerBlock;
    k_gather<0><<<grid, B>>>((float2*)out, N);
    k_gather<1><<<grid, B>>>((float2*)out, N);
}

// round 7
// speedup vs baseline: 1.0596x; 1.0596x over previous
#include <cuda_runtime.h>
#include <cuda_bf16.h>
#include <cuda_fp16.h>
#include <cstdint>

// LightGCN via pull-based CSR gather, fp16 intermediate embeddings.
// deg = clamp(segsum(w by dst), 1); norm = deg^-1/2
// repeat 2x: h = segsum((h*norm)[src] * w, by dst) * norm
// out = mean(h0, h1, h2)  -- assembled only in the final gather.

#define NN     100000
#define EE     1600000
#define SCAN_B 256                       // nodes per scan block
#define NB_MAX 512                       // >= ceil(NN/SCAN_B) = 391

__device__ float   g_deg[NN];
__device__ int     g_cnt[NN];
__device__ float   g_norm[NN];
__device__ int     g_rowptr[NN + 1];
__device__ int     g_cursor[NN];
__device__ int     g_bsum[NB_MAX];
__device__ float2  g_edge[EE];               // .x = __int_as_float(src), .y = w
__device__ __half2 g_ha[(size_t)NN * 32];    // layer-1 input (h0*norm), fp16
__device__ __half2 g_hb[(size_t)NN * 32];    // layer-2 input (h1*norm), fp16

// ---------------- CSR build ----------------

__global__ void k_zero(int n) {
    int i = blockIdx.x * blockDim.x + threadIdx.x;
    if (i < n) { g_deg[i] = 0.0f; g_cnt[i] = 0; }
}

__global__ void k_hist(const float* __restrict__ w,
                       const int* __restrict__ dst, int e) {
    int i = blockIdx.x * blockDim.x + threadIdx.x;
    if (i >= e) return;
    int d = dst[i];
    atomicAdd(&g_deg[d], w[i]);
    atomicAdd(&g_cnt[d], 1);
}

// Pass A: per-block (256-node) exclusive scan of g_cnt -> g_rowptr; totals -> g_bsum
__global__ void k_scanA(int n) {
    __shared__ int sh[8];
    int i = blockIdx.x * SCAN_B + threadIdx.x;
    int lane = threadIdx.x & 31, wid = threadIdx.x >> 5;
    int v = (i < n) ? g_cnt[i] : 0;
    int x = v;
    #pragma unroll
    for (int o = 1; o < 32; o <<= 1) {
        int y = __shfl_up_sync(0xffffffffu, x, o);
        if (lane >= o) x += y;
    }
    if (lane == 31) sh[wid] = x;
    __syncthreads();
    if (threadIdx.x == 0) {
        int acc = 0;
        #pragma unroll
        for (int k = 0; k < 8; k++) { int t = sh[k]; sh[k] = acc; acc += t; }
        g_bsum[blockIdx.x] = acc;                 // block total
    }
    __syncthreads();
    int excl = x - v + sh[wid];
    if (i < n) g_rowptr[i] = excl;
}

// Pass B+C+prep fused. 1024 threads/block, 256 nodes/block.
//  - threads 0..255: per-block prefix over g_bsum, finalize rowptr/cursor/norm
//  - all 1024 threads: prep 256 nodes x 16 float4: g_ha = fp16(h * norm)
__global__ void k_scanC(const float4* __restrict__ h, int n, int e) {
    __shared__ float s_norm[SCAN_B];
    __shared__ int s_off;
    int t = threadIdx.x;
    int lane = t & 31;
    int base = blockIdx.x * SCAN_B;

    if (t < 32) {
        int acc = 0;
        for (int k = lane; k < blockIdx.x; k += 32) acc += g_bsum[k];
        #pragma unroll
        for (int o = 16; o > 0; o >>= 1)
            acc += __shfl_down_sync(0xffffffffu, acc, o);
        if (lane == 0) s_off = acc;
    }
    __syncthreads();

    if (t < SCAN_B) {
        int i = base + t;
        float nm = 0.0f;
        if (i < n) {
            int r = g_rowptr[i] + s_off;
            g_rowptr[i] = r;
            g_cursor[i] = r;
            nm = rsqrtf(fmaxf(g_deg[i], 1.0f));
            g_norm[i] = nm;
            if (i == 0) g_rowptr[n] = e;
        }
        s_norm[t] = nm;
    }
    __syncthreads();

    // prep: 256 nodes * 16 float4 = 4096 float4, 1024 threads x 4 iters
    #pragma unroll
    for (int k = 0; k < 4; k++) {
        int idx4 = base * 16 + t + k * 1024;   // global float4 index
        int node = idx4 >> 4;
        if (node >= n) break;
        float nrm = s_norm[node - base];
        float4 v = h[idx4];
        g_ha[(size_t)idx4 * 2]     = __floats2half2_rn(v.x * nrm, v.y * nrm);
        g_ha[(size_t)idx4 * 2 + 1] = __floats2half2_rn(v.z * nrm, v.w * nrm);
    }
}

__global__ void k_fill(const int* __restrict__ src,
                       const int* __restrict__ dst,
                       const float* __restrict__ w, int e) {
    int i = blockIdx.x * blockDim.x + threadIdx.x;
    if (i >= e) return;
    int d = dst[i];
    int pos = atomicAdd(&g_cursor[d], 1);
    g_edge[pos] = make_float2(__int_as_float(src[i]), w[i]);
}

// ---------------- gather layers ----------------

// Warp per node; lane owns dims [2*lane, 2*lane+1] (one __half2).
// Edge metadata loads are warp-broadcast (cheap, L1); row loads are
// independent (unroll 8 -> MLP ~16).
// LAYER=0: read g_ha; g_hb = fp16(sum * norm^2). No out access.
// LAYER=1: read g_hb; out = (h0 + hb_own/norm + sum*norm) / 3.
template <int LAYER>
__global__ void k_gather(const float2* __restrict__ h2,
                         float2* __restrict__ out, int n) {
    const __half2* hin = (LAYER == 0) ? g_ha : g_hb;
    int warp = (blockIdx.x * blockDim.x + threadIdx.x) >> 5;
    int lane = threadIdx.x & 31;
    if (warp >= n) return;
    int beg = g_rowptr[warp];
    int end = g_rowptr[warp + 1];

    float ax = 0.f, ay = 0.f;
    int j = beg;
    for (; j + 8 <= end; j += 8) {
        float2 e0 = g_edge[j],   e1 = g_edge[j+1];
        float2 e2 = g_edge[j+2], e3 = g_edge[j+3];
        float2 e4 = g_edge[j+4], e5 = g_edge[j+5];
        float2 e6 = g_edge[j+6], e7 = g_edge[j+7];
        float2 v0 = __half22float2(hin[(size_t)__float_as_int(e0.x) * 32 + lane]);
        float2 v1 = __half22float2(hin[(size_t)__float_as_int(e1.x) * 32 + lane]);
        float2 v2 = __half22float2(hin[(size_t)__float_as_int(e2.x) * 32 + lane]);
        float2 v3 = __half22float2(hin[(size_t)__float_as_int(e3.x) * 32 + lane]);
        float2 v4 = __half22float2(hin[(size_t)__float_as_int(e4.x) * 32 + lane]);
        float2 v5 = __half22float2(hin[(size_t)__float_as_int(e5.x) * 32 + lane]);
        float2 v6 = __half22float2(hin[(size_t)__float_as_int(e6.x) * 32 + lane]);
        float2 v7 = __half22float2(hin[(size_t)__float_as_int(e7.x) * 32 + lane]);
        ax += v0.x * e0.y; ay += v0.y * e0.y;
        ax += v1.x * e1.y; ay += v1.y * e1.y;
        ax += v2.x * e2.y; ay += v2.y * e2.y;
        ax += v3.x * e3.y; ay += v3.y * e3.y;
        ax += v4.x * e4.y; ay += v4.y * e4.y;
        ax += v5.x * e5.y; ay += v5.y * e5.y;
        ax += v6.x * e6.y; ay += v6.y * e6.y;
        ax += v7.x * e7.y; ay += v7.y * e7.y;
    }
    for (; j < end; ++j) {
        float2 e = g_edge[j];
        float2 v = __half22float2(hin[(size_t)__float_as_int(e.x) * 32 + lane]);
        ax += v.x * e.y; ay += v.y * e.y;
    }

    float nm = g_norm[warp];
    size_t idx = (size_t)warp * 32 + lane;
    if (LAYER == 0) {
        float nm2 = nm * nm;                      // h1*norm = sum*norm^2
        g_hb[idx] = __floats2half2_rn(ax * nm2, ay * nm2);
    } else {
        float h2x = ax * nm, h2y = ay * nm;       // layer-2 output
        float rin = __frcp_rn(nm);                // 1/norm (norm in (0,1])
        float2 hbv = __half22float2(g_hb[idx]);
        float h1x = hbv.x * rin, h1y = hbv.y * rin;
        float2 h0 = h2[idx];
        const float third = 1.0f / 3.0f;
        out[idx] = make_float2((h0.x + h1x + h2x) * third,
                               (h0.y + h1y + h2y) * third);
    }
}

extern "C" void kernel_launch(void* const* d_in, const int* in_sizes, int n_in,
                              void* d_out, int out_size) {
    const float* h   = (const float*)d_in[0];
    const float* w   = (const float*)d_in[1];
    const int*   src = (const int*)d_in[2];
    const int*   dst = (const int*)d_in[3];
    float* out = (float*)d_out;

    const int N  = in_sizes[0] / 64;   // 100000
    const int E  = in_sizes[1];        // 1600000
    const int B  = 256;
    const int nb = (N + SCAN_B - 1) / SCAN_B;   // 391

    k_zero <<<(N + B - 1) / B, B>>>(N);
    k_hist <<<(E + B - 1) / B, B>>>(w, dst, E);
    k_scanA<<<nb, SCAN_B>>>(N);
    k_scanC<<<nb, 1024>>>((const float4*)h, N, E);
    k_fill <<<(E + B - 1) / B, B>>>(src, dst, w, E);

    const int warpsPerBlock = B / 32;
    const int grid = (N + warpsPerBlock - 1) / warpsPerBlock;
    k_gather<0><<<grid, B>>>((const float2*)h, (float2*)out, N);
    k_gather<1><<<grid, B>>>((const float2*)h, (float2*)out, N);
}